// round 3
// baseline (speedup 1.0000x reference)
#include <cuda_runtime.h>
#include <cuda_bf16.h>
#include <math.h>

// GCN 2-layer: out = tanh(GCNConv(x,W1,b1)) @ W2 + b2
// N=50000 nodes, E=640000 edges, D_in=D_hid=D_out=128.
//
// Decomposition:
//   deg[i]  = 1 + #edges(dst=i);  dinv[i] = rsqrt(deg[i])
//   hs      = rowscale(dinv) * (x @ W1)            (GEMM1, epilogue scale)
//   acc[i]  = hs[i] + sum_{e:dst=i} hs[src(e)]     (self-loop init + edge atomics)
//   t[i,k]  = tanh(dinv[i]*acc[i,k] + b1[k])       (fused into GEMM2 smem load)
//   out     = t @ W2 + b2                          (GEMM2)

#define N_NODES 50000
#define DIM     128

__device__ float g_h  [(size_t)N_NODES * DIM];  // hs = dinv[i] * (x@W1)[i]
__device__ float g_agg[(size_t)N_NODES * DIM];  // accumulator (init = hs, then edge adds)
__device__ float g_deg [N_NODES];
__device__ float g_dinv[N_NODES];

// ---------------------------------------------------------------- degree prep

__global__ void k_deg_init() {
    int i = blockIdx.x * blockDim.x + threadIdx.x;
    if (i < N_NODES) g_deg[i] = 1.0f;  // self-loop
}

__global__ void k_deg_count(const int* __restrict__ ei, int E) {
    int e = blockIdx.x * blockDim.x + threadIdx.x;
    if (e < E) atomicAdd(&g_deg[ei[E + e]], 1.0f);  // dst row of edge_index
}

__global__ void k_dinv() {
    int i = blockIdx.x * blockDim.x + threadIdx.x;
    if (i < N_NODES) g_dinv[i] = rsqrtf(g_deg[i]);
}

// ---------------------------------------------------------------- GEMM 1
// hs = rowscale(dinv) * (x @ W1); also initializes g_agg = hs (self-loop term).
// Block tile 64x128, thread tile 4x8, K chunked by 32.

__global__ __launch_bounds__(256) void k_gemm1(const float* __restrict__ x,
                                               const float* __restrict__ W) {
    __shared__ float xs[64][33];
    __shared__ float ws[32][128];
    const int tx = threadIdx.x & 15;
    const int ty = threadIdx.x >> 4;
    const int row0 = blockIdx.x * 64;

    float acc[4][8];
#pragma unroll
    for (int r = 0; r < 4; r++)
#pragma unroll
        for (int c = 0; c < 8; c++) acc[r][c] = 0.0f;

    for (int kt = 0; kt < DIM; kt += 32) {
#pragma unroll
        for (int i = 0; i < 8; i++) {          // 64x32 x-tile
            int idx = threadIdx.x + i * 256;
            int r = idx >> 5, k = idx & 31;
            int gr = row0 + r;
            xs[r][k] = (gr < N_NODES) ? x[(size_t)gr * DIM + kt + k] : 0.0f;
        }
#pragma unroll
        for (int i = 0; i < 16; i++) {         // 32x128 W-tile
            int idx = threadIdx.x + i * 256;
            int k = idx >> 7, n = idx & 127;
            ws[k][n] = W[(size_t)(kt + k) * DIM + n];
        }
        __syncthreads();
#pragma unroll
        for (int kk = 0; kk < 32; kk++) {
            float a[4], b[8];
#pragma unroll
            for (int r = 0; r < 4; r++) a[r] = xs[ty * 4 + r][kk];
#pragma unroll
            for (int c = 0; c < 8; c++) b[c] = ws[kk][tx + c * 16];
#pragma unroll
            for (int r = 0; r < 4; r++)
#pragma unroll
                for (int c = 0; c < 8; c++) acc[r][c] = fmaf(a[r], b[c], acc[r][c]);
        }
        __syncthreads();
    }

#pragma unroll
    for (int r = 0; r < 4; r++) {
        int gr = row0 + ty * 4 + r;
        if (gr < N_NODES) {
            float s = g_dinv[gr];
#pragma unroll
            for (int c = 0; c < 8; c++) {
                int col = tx + c * 16;
                float v = s * acc[r][c];
                g_h  [(size_t)gr * DIM + col] = v;
                g_agg[(size_t)gr * DIM + col] = v;  // self-loop contribution
            }
        }
    }
}

// ---------------------------------------------------------------- edge agg
// One warp per edge: float4 gather of hs[src], vector RED into acc[dst].

__device__ __forceinline__ void red_add_f32x4(float* p, float4 v) {
    asm volatile("red.global.add.v4.f32 [%0], {%1,%2,%3,%4};"
                 :: "l"(p), "f"(v.x), "f"(v.y), "f"(v.z), "f"(v.w) : "memory");
}

__global__ __launch_bounds__(256) void k_edge(const int* __restrict__ ei, int E) {
    int warp = (blockIdx.x * blockDim.x + threadIdx.x) >> 5;
    int lane = threadIdx.x & 31;
    if (warp >= E) return;
    int src = ei[warp];
    int dst = ei[E + warp];
    const float4* hrow = (const float4*)(g_h + (size_t)src * DIM);
    float4 v = hrow[lane];                         // 32 lanes x 16B = 512B row
    float* orow = g_agg + (size_t)dst * DIM + lane * 4;
    red_add_f32x4(orow, v);
}

// ---------------------------------------------------------------- GEMM 2
// out = tanh(rowscale(dinv)*acc + b1) @ W2 + b2; tanh fused into smem load.

__global__ __launch_bounds__(256) void k_gemm2(const float* __restrict__ W,
                                               const float* __restrict__ b1,
                                               const float* __restrict__ b2,
                                               float* __restrict__ out) {
    __shared__ float xs[64][33];
    __shared__ float ws[32][128];
    const int tx = threadIdx.x & 15;
    const int ty = threadIdx.x >> 4;
    const int row0 = blockIdx.x * 64;

    float acc[4][8];
#pragma unroll
    for (int r = 0; r < 4; r++)
#pragma unroll
        for (int c = 0; c < 8; c++) acc[r][c] = 0.0f;

    for (int kt = 0; kt < DIM; kt += 32) {
#pragma unroll
        for (int i = 0; i < 8; i++) {
            int idx = threadIdx.x + i * 256;
            int r = idx >> 5, k = idx & 31;
            int gr = row0 + r;
            float t = 0.0f;
            if (gr < N_NODES) {
                float v = g_agg[(size_t)gr * DIM + kt + k];
                t = tanhf(g_dinv[gr] * v + b1[kt + k]);
            }
            xs[r][k] = t;
        }
#pragma unroll
        for (int i = 0; i < 16; i++) {
            int idx = threadIdx.x + i * 256;
            int k = idx >> 7, n = idx & 127;
            ws[k][n] = W[(size_t)(kt + k) * DIM + n];
        }
        __syncthreads();
#pragma unroll
        for (int kk = 0; kk < 32; kk++) {
            float a[4], b[8];
#pragma unroll
            for (int r = 0; r < 4; r++) a[r] = xs[ty * 4 + r][kk];
#pragma unroll
            for (int c = 0; c < 8; c++) b[c] = ws[kk][tx + c * 16];
#pragma unroll
            for (int r = 0; r < 4; r++)
#pragma unroll
                for (int c = 0; c < 8; c++) acc[r][c] = fmaf(a[r], b[c], acc[r][c]);
        }
        __syncthreads();
    }

#pragma unroll
    for (int r = 0; r < 4; r++) {
        int gr = row0 + ty * 4 + r;
        if (gr < N_NODES) {
#pragma unroll
            for (int c = 0; c < 8; c++) {
                int col = tx + c * 16;
                out[(size_t)gr * DIM + col] = acc[r][c] + b2[col];
            }
        }
    }
}

// ---------------------------------------------------------------- launch

extern "C" void kernel_launch(void* const* d_in, const int* in_sizes, int n_in,
                              void* d_out, int out_size) {
    const float* x  = (const float*)d_in[0];
    const int*   ei = (const int*)  d_in[1];
    const float* W1 = (const float*)d_in[2];
    const float* b1 = (const float*)d_in[3];
    const float* W2 = (const float*)d_in[4];
    const float* b2 = (const float*)d_in[5];
    float* out = (float*)d_out;

    const int E = in_sizes[1] / 2;

    k_deg_init <<<(N_NODES + 255) / 256, 256>>>();
    k_deg_count<<<(E + 255) / 256, 256>>>(ei, E);
    k_dinv     <<<(N_NODES + 255) / 256, 256>>>();
    k_gemm1    <<<(N_NODES + 63) / 64, 256>>>(x, W1);
    k_edge     <<<(E + 7) / 8, 256>>>(ei, E);       // 8 warps/block, 1 warp/edge
    k_gemm2    <<<(N_NODES + 63) / 64, 256>>>(W2, b1, b2, out);
}

// round 5
// speedup vs baseline: 1.2275x; 1.2275x over previous
#include <cuda_runtime.h>
#include <cuda_bf16.h>
#include <math.h>

// GCN 2-layer: out = tanh(GCNConv(x,W1,b1)) @ W2 + b2
// N=50000 nodes, E=640000 edges, D=128.
//
//   cnt[i]  = #edges(dst=i); dinv[i] = rsqrt(cnt[i]+1)
//   CSR: rowptr (exclusive scan of cnt), eidx (src ids grouped by dst)
//   hs      = rowscale(dinv) * (x @ W1)                   (GEMM1)
//   agg[i]  = hs[i] + sum_{j in nbr_in(i)} hs[j]          (CSR pull, no atomics)
//   t[i,k]  = tanh(dinv[i]*agg[i,k] + b1[k])              (fused into GEMM2 load)
//   out     = t @ W2 + b2                                 (GEMM2)

#define N_NODES 50000
#define MAX_E   640000
#define DIM     128

__device__ float g_h   [(size_t)N_NODES * DIM];
__device__ float g_agg [(size_t)N_NODES * DIM];
__device__ float g_dinv[N_NODES];
__device__ int   g_cnt [N_NODES];
__device__ int   g_rowptr[N_NODES + 1];
__device__ int   g_wcur[N_NODES];
__device__ int   g_eidx[MAX_E];

// ---------------------------------------------------------------- CSR build

__global__ void k_zero() {
    int i = blockIdx.x * blockDim.x + threadIdx.x;
    if (i < N_NODES) g_cnt[i] = 0;
}

__global__ void k_count(const int* __restrict__ ei, int E) {
    int e = blockIdx.x * blockDim.x + threadIdx.x;
    if (e < E) atomicAdd(&g_cnt[ei[E + e]], 1);
}

// Single-block scan (1024 threads): exclusive prefix of g_cnt -> rowptr/wcur,
// plus dinv = rsqrt(cnt+1).
__global__ __launch_bounds__(1024) void k_scan() {
    __shared__ int wsum[32];
    __shared__ int carry;
    const int t = threadIdx.x, lane = t & 31, wid = t >> 5;
    if (t == 0) carry = 0;
    __syncthreads();

    for (int base = 0; base < N_NODES; base += 1024) {
        int i = base + t;
        int v = (i < N_NODES) ? g_cnt[i] : 0;
        int c = carry;

        // warp inclusive scan
        int x = v;
#pragma unroll
        for (int o = 1; o < 32; o <<= 1) {
            int y = __shfl_up_sync(0xffffffffu, x, o);
            if (lane >= o) x += y;
        }
        if (lane == 31) wsum[wid] = x;
        __syncthreads();
        if (wid == 0) {
            int w = wsum[lane];
#pragma unroll
            for (int o = 1; o < 32; o <<= 1) {
                int y = __shfl_up_sync(0xffffffffu, w, o);
                if (lane >= o) w += y;
            }
            wsum[lane] = w;  // inclusive warp totals
        }
        __syncthreads();
        int woff = (wid == 0) ? 0 : wsum[wid - 1];
        int excl = c + woff + x - v;
        if (i < N_NODES) {
            g_rowptr[i] = excl;
            g_wcur[i]   = excl;
            g_dinv[i]   = rsqrtf((float)v + 1.0f);
        }
        __syncthreads();
        if (t == 1023) carry = c + wsum[31];
        __syncthreads();
    }
    if (t == 0) g_rowptr[N_NODES] = carry;
}

__global__ void k_fill(const int* __restrict__ ei, int E) {
    int e = blockIdx.x * blockDim.x + threadIdx.x;
    if (e < E) {
        int src = ei[e];
        int dst = ei[E + e];
        int pos = atomicAdd(&g_wcur[dst], 1);
        g_eidx[pos] = src;
    }
}

// ---------------------------------------------------------------- GEMM 1
// g_h = rowscale(dinv) * (x @ W1)
// 128x128 block tile, 256 threads, 8x8 thread tile (4+4 split), BK=16.

__global__ __launch_bounds__(256) void k_gemm1(const float* __restrict__ x,
                                               const float* __restrict__ W) {
    __shared__ float At[16][132];   // transposed A tile
    __shared__ float Bs[16][128];

    const int tx = threadIdx.x & 15;       // col group
    const int ty = threadIdx.x >> 4;       // row group
    const int row0 = blockIdx.x * 128;

    // A-load mapping: row lr, float4 k-groups lg and lg+2
    const int lr = threadIdx.x & 127;
    const int lg = threadIdx.x >> 7;
    const int arow = min(row0 + lr, N_NODES - 1);
    // B-load mapping
    const int bk = threadIdx.x >> 5;
    const int bn = (threadIdx.x & 31) * 4;

    float acc[8][8];
#pragma unroll
    for (int i = 0; i < 8; i++)
#pragma unroll
        for (int j = 0; j < 8; j++) acc[i][j] = 0.0f;

    for (int kt = 0; kt < DIM; kt += 16) {
        float4 a0 = *(const float4*)&x[(size_t)arow * DIM + kt + lg * 4];
        float4 a1 = *(const float4*)&x[(size_t)arow * DIM + kt + lg * 4 + 8];
        float4 w0 = *(const float4*)&W[(size_t)(kt + bk) * DIM + bn];
        float4 w1 = *(const float4*)&W[(size_t)(kt + bk + 8) * DIM + bn];
        At[lg * 4 + 0][lr] = a0.x; At[lg * 4 + 1][lr] = a0.y;
        At[lg * 4 + 2][lr] = a0.z; At[lg * 4 + 3][lr] = a0.w;
        At[lg * 4 + 8][lr] = a1.x; At[lg * 4 + 9][lr] = a1.y;
        At[lg * 4 + 10][lr] = a1.z; At[lg * 4 + 11][lr] = a1.w;
        *(float4*)&Bs[bk][bn] = w0;
        *(float4*)&Bs[bk + 8][bn] = w1;
        __syncthreads();

#pragma unroll
        for (int kk = 0; kk < 16; kk++) {
            float4 av0 = *(const float4*)&At[kk][ty * 4];
            float4 av1 = *(const float4*)&At[kk][64 + ty * 4];
            float4 bv0 = *(const float4*)&Bs[kk][tx * 4];
            float4 bv1 = *(const float4*)&Bs[kk][64 + tx * 4];
            float a[8] = {av0.x, av0.y, av0.z, av0.w, av1.x, av1.y, av1.z, av1.w};
            float b[8] = {bv0.x, bv0.y, bv0.z, bv0.w, bv1.x, bv1.y, bv1.z, bv1.w};
#pragma unroll
            for (int i = 0; i < 8; i++)
#pragma unroll
                for (int j = 0; j < 8; j++) acc[i][j] = fmaf(a[i], b[j], acc[i][j]);
        }
        __syncthreads();
    }

#pragma unroll
    for (int i = 0; i < 8; i++) {
        int gr = row0 + ((i < 4) ? (ty * 4 + i) : (64 + ty * 4 + i - 4));
        if (gr < N_NODES) {
            float s = g_dinv[gr];
            float4 o0 = make_float4(s * acc[i][0], s * acc[i][1], s * acc[i][2], s * acc[i][3]);
            float4 o1 = make_float4(s * acc[i][4], s * acc[i][5], s * acc[i][6], s * acc[i][7]);
            *(float4*)&g_h[(size_t)gr * DIM + tx * 4]      = o0;
            *(float4*)&g_h[(size_t)gr * DIM + 64 + tx * 4] = o1;
        }
    }
}

// ---------------------------------------------------------------- aggregate
// One warp per dst node: acc = hs[dst] + sum hs[src], plain store (no atomics).

__global__ __launch_bounds__(256) void k_aggregate() {
    int node = blockIdx.x * 8 + (threadIdx.x >> 5);
    int lane = threadIdx.x & 31;
    if (node >= N_NODES) return;

    float4 acc = ((const float4*)(g_h + (size_t)node * DIM))[lane];  // self-loop
    int j   = g_rowptr[node];
    int end = g_rowptr[node + 1];

    for (; j + 2 <= end; j += 2) {
        int s0 = g_eidx[j];
        int s1 = g_eidx[j + 1];
        float4 v0 = ((const float4*)(g_h + (size_t)s0 * DIM))[lane];
        float4 v1 = ((const float4*)(g_h + (size_t)s1 * DIM))[lane];
        acc.x += v0.x; acc.y += v0.y; acc.z += v0.z; acc.w += v0.w;
        acc.x += v1.x; acc.y += v1.y; acc.z += v1.z; acc.w += v1.w;
    }
    if (j < end) {
        int s0 = g_eidx[j];
        float4 v0 = ((const float4*)(g_h + (size_t)s0 * DIM))[lane];
        acc.x += v0.x; acc.y += v0.y; acc.z += v0.z; acc.w += v0.w;
    }
    ((float4*)(g_agg + (size_t)node * DIM))[lane] = acc;
}

// ---------------------------------------------------------------- GEMM 2
// out = tanh(rowscale(dinv)*agg + b1) @ W2 + b2; tanh fused into A-tile load.

__global__ __launch_bounds__(256) void k_gemm2(const float* __restrict__ W,
                                               const float* __restrict__ b1,
                                               const float* __restrict__ b2,
                                               float* __restrict__ out) {
    __shared__ float At[16][132];
    __shared__ float Bs[16][128];

    const int tx = threadIdx.x & 15;
    const int ty = threadIdx.x >> 4;
    const int row0 = blockIdx.x * 128;

    const int lr = threadIdx.x & 127;
    const int lg = threadIdx.x >> 7;
    const int arow = min(row0 + lr, N_NODES - 1);
    const float s = g_dinv[arow];
    const int bk = threadIdx.x >> 5;
    const int bn = (threadIdx.x & 31) * 4;

    float acc[8][8];
#pragma unroll
    for (int i = 0; i < 8; i++)
#pragma unroll
        for (int j = 0; j < 8; j++) acc[i][j] = 0.0f;

    for (int kt = 0; kt < DIM; kt += 16) {
        float4 a0 = *(const float4*)&g_agg[(size_t)arow * DIM + kt + lg * 4];
        float4 a1 = *(const float4*)&g_agg[(size_t)arow * DIM + kt + lg * 4 + 8];
        float4 c0 = *(const float4*)&b1[kt + lg * 4];
        float4 c1 = *(const float4*)&b1[kt + lg * 4 + 8];
        float4 w0 = *(const float4*)&W[(size_t)(kt + bk) * DIM + bn];
        float4 w1 = *(const float4*)&W[(size_t)(kt + bk + 8) * DIM + bn];
        At[lg * 4 + 0][lr] = tanhf(fmaf(s, a0.x, c0.x));
        At[lg * 4 + 1][lr] = tanhf(fmaf(s, a0.y, c0.y));
        At[lg * 4 + 2][lr] = tanhf(fmaf(s, a0.z, c0.z));
        At[lg * 4 + 3][lr] = tanhf(fmaf(s, a0.w, c0.w));
        At[lg * 4 + 8][lr] = tanhf(fmaf(s, a1.x, c1.x));
        At[lg * 4 + 9][lr] = tanhf(fmaf(s, a1.y, c1.y));
        At[lg * 4 + 10][lr] = tanhf(fmaf(s, a1.z, c1.z));
        At[lg * 4 + 11][lr] = tanhf(fmaf(s, a1.w, c1.w));
        *(float4*)&Bs[bk][bn] = w0;
        *(float4*)&Bs[bk + 8][bn] = w1;
        __syncthreads();

#pragma unroll
        for (int kk = 0; kk < 16; kk++) {
            float4 av0 = *(const float4*)&At[kk][ty * 4];
            float4 av1 = *(const float4*)&At[kk][64 + ty * 4];
            float4 bv0 = *(const float4*)&Bs[kk][tx * 4];
            float4 bv1 = *(const float4*)&Bs[kk][64 + tx * 4];
            float a[8] = {av0.x, av0.y, av0.z, av0.w, av1.x, av1.y, av1.z, av1.w};
            float b[8] = {bv0.x, bv0.y, bv0.z, bv0.w, bv1.x, bv1.y, bv1.z, bv1.w};
#pragma unroll
            for (int i = 0; i < 8; i++)
#pragma unroll
                for (int j = 0; j < 8; j++) acc[i][j] = fmaf(a[i], b[j], acc[i][j]);
        }
        __syncthreads();
    }

    float4 d0 = *(const float4*)&b2[tx * 4];
    float4 d1 = *(const float4*)&b2[64 + tx * 4];
#pragma unroll
    for (int i = 0; i < 8; i++) {
        int gr = row0 + ((i < 4) ? (ty * 4 + i) : (64 + ty * 4 + i - 4));
        if (gr < N_NODES) {
            float4 o0 = make_float4(acc[i][0] + d0.x, acc[i][1] + d0.y,
                                    acc[i][2] + d0.z, acc[i][3] + d0.w);
            float4 o1 = make_float4(acc[i][4] + d1.x, acc[i][5] + d1.y,
                                    acc[i][6] + d1.z, acc[i][7] + d1.w);
            *(float4*)&out[(size_t)gr * DIM + tx * 4]      = o0;
            *(float4*)&out[(size_t)gr * DIM + 64 + tx * 4] = o1;
        }
    }
}

// ---------------------------------------------------------------- launch

extern "C" void kernel_launch(void* const* d_in, const int* in_sizes, int n_in,
                              void* d_out, int out_size) {
    const float* x  = (const float*)d_in[0];
    const int*   ei = (const int*)  d_in[1];
    const float* W1 = (const float*)d_in[2];
    const float* b1 = (const float*)d_in[3];
    const float* W2 = (const float*)d_in[4];
    const float* b2 = (const float*)d_in[5];
    float* out = (float*)d_out;

    const int E = in_sizes[1] / 2;

    k_zero     <<<(N_NODES + 255) / 256, 256>>>();
    k_count    <<<(E + 255) / 256, 256>>>(ei, E);
    k_scan     <<<1, 1024>>>();
    k_fill     <<<(E + 255) / 256, 256>>>(ei, E);
    k_gemm1    <<<(N_NODES + 127) / 128, 256>>>(x, W1);
    k_aggregate<<<(N_NODES + 7) / 8, 256>>>();
    k_gemm2    <<<(N_NODES + 127) / 128, 256>>>(W2, b1, b2, out);
}

// round 16
// speedup vs baseline: 2.0890x; 1.7018x over previous
#include <cuda_runtime.h>
#include <cuda_bf16.h>
#include <math.h>
#include <stdint.h>

// GCN 2-layer: out = tanh(GCNConv(x,W1,b1)) @ W2 + b2
// N=50000, E=640000, D=128.
//
//   CSR build (count -> 3-phase scan -> fill)
//   hs    = rowscale(dinv) * (x @ W1)           [mma.sync bf16-split GEMM]
//   agg[i]= hs[i] + sum_{j in nbr(i)} hs[j]     [CSR pull, no atomics]
//   out   = tanh(rowscale(dinv)*agg + b1) @ W2 + b2   [mma.sync GEMM, fused]
//
// GEMM: fp32 split into bf16 hi/lo; D = Ah@Wh + Ah@Wl + Al@Wh (err ~2^-17).
// CRITICAL RULE (R10/R15 bug): never pass __device__ symbols as kernel
// arguments from host code — host sees the HOST SHADOW, and GB300's ATS
// makes the bad access silently "work" (writes go to host memory, device
// copy stays zero). All internal buffers are referenced device-side.

#define N_NODES 50000
#define MAX_E   640000
#define DIM     128
#define MTILE   64
#define NT2     ((N_NODES + MTILE - 1) / MTILE)  // 782
#define SCAN_B  ((N_NODES + 1023) / 1024)        // 49
#define SA      136                               // padded row stride (bf16)

__device__ float g_h   [(size_t)N_NODES * DIM];
__device__ float g_agg [(size_t)N_NODES * DIM];
__device__ float g_dinv[N_NODES];
__device__ int   g_cnt [N_NODES];
__device__ int   g_rowptr[N_NODES + 1];
__device__ int   g_wcur[N_NODES];
__device__ int   g_eidx[MAX_E];
__device__ int   g_bsum[SCAN_B + 1];
// [W1/W2][hi/lo] transposed images: Wt[n][k], row stride SA, 16B aligned.
__device__ __align__(16) __nv_bfloat16 g_wimg[2][2][DIM * SA];

// ================================================================ CSR build

__global__ void k_zero() {
    int i = blockIdx.x * blockDim.x + threadIdx.x;
    if (i < N_NODES) g_cnt[i] = 0;
}

__global__ void k_count(const int* __restrict__ ei, int E) {
    int e = (blockIdx.x * blockDim.x + threadIdx.x) * 2;
    if (e + 1 < E) {
        int2 d = *(const int2*)&ei[E + e];
        atomicAdd(&g_cnt[d.x], 1);
        atomicAdd(&g_cnt[d.y], 1);
    } else if (e < E) {
        atomicAdd(&g_cnt[ei[E + e]], 1);
    }
}

__global__ __launch_bounds__(1024) void k_scan_block() {
    __shared__ int wsum[32];
    const int t = threadIdx.x, lane = t & 31, wid = t >> 5;
    const int i = blockIdx.x * 1024 + t;
    int v = (i < N_NODES) ? g_cnt[i] : 0;

    int x = v;
#pragma unroll
    for (int o = 1; o < 32; o <<= 1) {
        int y = __shfl_up_sync(0xffffffffu, x, o);
        if (lane >= o) x += y;
    }
    if (lane == 31) wsum[wid] = x;
    __syncthreads();
    if (wid == 0) {
        int w = wsum[lane];
#pragma unroll
        for (int o = 1; o < 32; o <<= 1) {
            int y = __shfl_up_sync(0xffffffffu, w, o);
            if (lane >= o) w += y;
        }
        wsum[lane] = w;
    }
    __syncthreads();
    int woff = (wid == 0) ? 0 : wsum[wid - 1];
    if (i < N_NODES) {
        g_rowptr[i] = woff + x - v;   // block-local exclusive
        g_dinv[i]   = rsqrtf((float)v + 1.0f);
    }
    if (t == 0) g_bsum[blockIdx.x] = wsum[31];
}

__global__ void k_scan_tops(int nb) {
    int acc = 0;
    for (int b = 0; b < nb; b++) { int v = g_bsum[b]; g_bsum[b] = acc; acc += v; }
}

__global__ __launch_bounds__(1024) void k_scan_add(int E) {
    int i = blockIdx.x * 1024 + threadIdx.x;
    if (i < N_NODES) {
        int r = g_rowptr[i] + g_bsum[blockIdx.x];
        g_rowptr[i] = r;
        g_wcur[i]   = r;
        if (i == N_NODES - 1) g_rowptr[N_NODES] = E;
    }
}

__global__ void k_fill(const int* __restrict__ ei, int E) {
    int e = (blockIdx.x * blockDim.x + threadIdx.x) * 2;
    if (e + 1 < E) {
        int2 s = *(const int2*)&ei[e];
        int2 d = *(const int2*)&ei[E + e];
        g_eidx[atomicAdd(&g_wcur[d.x], 1)] = s.x;
        g_eidx[atomicAdd(&g_wcur[d.y], 1)] = s.y;
    } else if (e < E) {
        g_eidx[atomicAdd(&g_wcur[ei[E + e]], 1)] = ei[e];
    }
}

// ================================================================ W images
// W gmem is [K, N] (K-major rows). Build Wt[n][k] bf16 hi/lo, stride SA.
// grid=8: blockIdx>>2 selects W1/W2, blockIdx&3 selects quarter.

__global__ __launch_bounds__(256) void k_wconv(const float* __restrict__ W1,
                                               const float* __restrict__ W2) {
    const int w = blockIdx.x >> 2;
    const float* W = (w == 0) ? W1 : W2;
    __nv_bfloat16* dh = g_wimg[w][0];
    __nv_bfloat16* dl = g_wimg[w][1];
#pragma unroll
    for (int i = 0; i < 8; i++) {
        int p = (blockIdx.x & 3) * 2048 + i * 256 + threadIdx.x;  // 0..8191 pairs
        int n = p >> 6;
        int k0 = (p & 63) * 2;
        float f0 = W[(size_t)k0 * DIM + n];
        float f1 = W[(size_t)(k0 + 1) * DIM + n];
        __nv_bfloat16 h0 = __float2bfloat16(f0);
        __nv_bfloat16 h1 = __float2bfloat16(f1);
        __nv_bfloat16 l0 = __float2bfloat16(f0 - __bfloat162float(h0));
        __nv_bfloat16 l1 = __float2bfloat16(f1 - __bfloat162float(h1));
        *(__nv_bfloat162*)(dh + n * SA + k0) = __nv_bfloat162(h0, h1);
        *(__nv_bfloat162*)(dl + n * SA + k0) = __nv_bfloat162(l0, l1);
    }
}

// ================================================================ mma GEMM
// One CTA = 64x128x128 tile, 8 warps in 2(m)x4(n), each warp 32m x 32n.
// A hi/lo in static smem; W hi/lo fragments loaded from gmem (L2-hot).
// mode 0: g_h = dinv*(x@W1), A = Ain (x).
// mode 1: out = tanh(dinv*agg+b1)@W2 + b2, A = g_agg (device-side ref).

__device__ __forceinline__ void mma16816(float d[4], const uint32_t a[4],
                                         const uint32_t b[2]) {
    asm volatile(
        "mma.sync.aligned.m16n8k16.row.col.f32.bf16.bf16.f32 "
        "{%0,%1,%2,%3}, {%4,%5,%6,%7}, {%8,%9}, {%0,%1,%2,%3};"
        : "+f"(d[0]), "+f"(d[1]), "+f"(d[2]), "+f"(d[3])
        : "r"(a[0]), "r"(a[1]), "r"(a[2]), "r"(a[3]), "r"(b[0]), "r"(b[1]));
}

__global__ __launch_bounds__(256) void k_gemm_mma(
    const float* __restrict__ Ain,
    const float* __restrict__ b1,
    const float* __restrict__ b2,
    float* __restrict__ outw,
    int mode)
{
    __shared__ __nv_bfloat16 Ah[MTILE * SA];   // 17408 B
    __shared__ __nv_bfloat16 Al[MTILE * SA];   // 17408 B  (total 34816 < 48K)

    // device-side selection of internal buffers (NEVER via host args)
    const float* __restrict__ A = (mode == 0) ? Ain : (const float*)g_agg;
    float* __restrict__ outp    = (mode == 0) ? (float*)g_h : outw;
    const __nv_bfloat16* __restrict__ whp = g_wimg[mode][0];
    const __nv_bfloat16* __restrict__ wlp = g_wimg[mode][1];

    const int tid = threadIdx.x;
    const int row0 = blockIdx.x * MTILE;

    // A tile -> bf16 hi/lo (tanh/b1/dinv fused for mode 1): 4096 pairs
#pragma unroll 4
    for (int i = 0; i < 16; i++) {
        int q = i * 256 + tid;          // 0..4095
        int r = q >> 6;                 // 0..63
        int c = (q & 63) * 2;
        int gr = row0 + r;
        if (gr >= N_NODES) gr = N_NODES - 1;
        float2 v = *(const float2*)&A[(size_t)gr * DIM + c];
        if (mode == 1) {
            float s = g_dinv[gr];
            v.x = tanhf(fmaf(s, v.x, b1[c]));
            v.y = tanhf(fmaf(s, v.y, b1[c + 1]));
        }
        __nv_bfloat16 hx = __float2bfloat16(v.x);
        __nv_bfloat16 hy = __float2bfloat16(v.y);
        __nv_bfloat16 lx = __float2bfloat16(v.x - __bfloat162float(hx));
        __nv_bfloat16 ly = __float2bfloat16(v.y - __bfloat162float(hy));
        *(__nv_bfloat162*)(Ah + r * SA + c) = __nv_bfloat162(hx, hy);
        *(__nv_bfloat162*)(Al + r * SA + c) = __nv_bfloat162(lx, ly);
    }
    __syncthreads();

    const int wid = tid >> 5, lane = tid & 31;
    const int wm = (wid >> 2) * 32;     // warp m offset (0 or 32)
    const int wn = (wid & 3) * 32;      // warp n offset
    const int grp = lane >> 2;          // 0..7
    const int thr = lane & 3;           // 0..3

    float acc[2][4][4];
#pragma unroll
    for (int mi = 0; mi < 2; mi++)
#pragma unroll
        for (int ni = 0; ni < 4; ni++)
#pragma unroll
            for (int e = 0; e < 4; e++) acc[mi][ni][e] = 0.0f;

#pragma unroll 1
    for (int ks = 0; ks < 8; ks++) {
        const int kb = ks * 16;
        uint32_t bh[4][2], bl[4][2];
#pragma unroll
        for (int ni = 0; ni < 4; ni++) {   // W fragments from gmem (L2-hot)
            const __nv_bfloat16* pn = whp + (wn + ni * 8 + grp) * SA + kb + thr * 2;
            bh[ni][0] = *(const uint32_t*)pn;
            bh[ni][1] = *(const uint32_t*)(pn + 8);
            const __nv_bfloat16* pl = wlp + (wn + ni * 8 + grp) * SA + kb + thr * 2;
            bl[ni][0] = *(const uint32_t*)pl;
            bl[ni][1] = *(const uint32_t*)(pl + 8);
        }
        uint32_t ah[2][4], al[2][4];
#pragma unroll
        for (int mi = 0; mi < 2; mi++) {   // A fragments from smem
            const char* ba = (const char*)(Ah + (wm + mi * 16 + grp) * SA + kb + thr * 2);
            ah[mi][0] = *(const uint32_t*)(ba);
            ah[mi][1] = *(const uint32_t*)(ba + 8 * SA * 2);
            ah[mi][2] = *(const uint32_t*)(ba + 16);
            ah[mi][3] = *(const uint32_t*)(ba + 8 * SA * 2 + 16);
            const char* bb = (const char*)(Al + (wm + mi * 16 + grp) * SA + kb + thr * 2);
            al[mi][0] = *(const uint32_t*)(bb);
            al[mi][1] = *(const uint32_t*)(bb + 8 * SA * 2);
            al[mi][2] = *(const uint32_t*)(bb + 16);
            al[mi][3] = *(const uint32_t*)(bb + 8 * SA * 2 + 16);
        }
#pragma unroll
        for (int mi = 0; mi < 2; mi++)
#pragma unroll
            for (int ni = 0; ni < 4; ni++) {
                mma16816(acc[mi][ni], ah[mi], bh[ni]);
                mma16816(acc[mi][ni], ah[mi], bl[ni]);
                mma16816(acc[mi][ni], al[mi], bh[ni]);
            }
    }

    // epilogue
#pragma unroll
    for (int mi = 0; mi < 2; mi++) {
#pragma unroll
        for (int half = 0; half < 2; half++) {
            int gr = row0 + wm + mi * 16 + grp + half * 8;
            if (gr >= N_NODES) continue;
            float* orow = outp + (size_t)gr * DIM;
            if (mode == 0) {
                float s = g_dinv[gr];
#pragma unroll
                for (int ni = 0; ni < 4; ni++) {
                    int c = wn + ni * 8 + thr * 2;
                    float2 o = make_float2(s * acc[mi][ni][half * 2 + 0],
                                           s * acc[mi][ni][half * 2 + 1]);
                    *(float2*)(orow + c) = o;
                }
            } else {
#pragma unroll
                for (int ni = 0; ni < 4; ni++) {
                    int c = wn + ni * 8 + thr * 2;
                    float2 bb = *(const float2*)&b2[c];
                    float2 o = make_float2(acc[mi][ni][half * 2 + 0] + bb.x,
                                           acc[mi][ni][half * 2 + 1] + bb.y);
                    *(float2*)(orow + c) = o;
                }
            }
        }
    }
}

// ================================================================ aggregate
// One warp per dst node: acc = hs[dst] + sum hs[src], plain store.

__global__ __launch_bounds__(256) void k_aggregate() {
    int node = blockIdx.x * 8 + (threadIdx.x >> 5);
    int lane = threadIdx.x & 31;
    if (node >= N_NODES) return;

    float4 acc = ((const float4*)(g_h + (size_t)node * DIM))[lane];  // self-loop
    int j   = g_rowptr[node];
    int end = g_rowptr[node + 1];

    for (; j + 4 <= end; j += 4) {
        int s0 = g_eidx[j], s1 = g_eidx[j + 1], s2 = g_eidx[j + 2], s3 = g_eidx[j + 3];
        float4 v0 = ((const float4*)(g_h + (size_t)s0 * DIM))[lane];
        float4 v1 = ((const float4*)(g_h + (size_t)s1 * DIM))[lane];
        float4 v2 = ((const float4*)(g_h + (size_t)s2 * DIM))[lane];
        float4 v3 = ((const float4*)(g_h + (size_t)s3 * DIM))[lane];
        acc.x += v0.x + v1.x + v2.x + v3.x;
        acc.y += v0.y + v1.y + v2.y + v3.y;
        acc.z += v0.z + v1.z + v2.z + v3.z;
        acc.w += v0.w + v1.w + v2.w + v3.w;
    }
    for (; j < end; j++) {
        int s0 = g_eidx[j];
        float4 v0 = ((const float4*)(g_h + (size_t)s0 * DIM))[lane];
        acc.x += v0.x; acc.y += v0.y; acc.z += v0.z; acc.w += v0.w;
    }
    ((float4*)(g_agg + (size_t)node * DIM))[lane] = acc;
}

// ================================================================ launch

extern "C" void kernel_launch(void* const* d_in, const int* in_sizes, int n_in,
                              void* d_out, int out_size) {
    const float* x  = (const float*)d_in[0];
    const int*   ei = (const int*)  d_in[1];
    const float* W1 = (const float*)d_in[2];
    const float* b1 = (const float*)d_in[3];
    const float* W2 = (const float*)d_in[4];
    const float* b2 = (const float*)d_in[5];
    float* out = (float*)d_out;

    const int E = in_sizes[1] / 2;

    k_wconv     <<<8, 256>>>(W1, W2);
    k_zero      <<<(N_NODES + 255) / 256, 256>>>();
    k_count     <<<(E / 2 + 255) / 256, 256>>>(ei, E);
    k_scan_block<<<SCAN_B, 1024>>>();
    k_scan_tops <<<1, 1>>>(SCAN_B);
    k_scan_add  <<<SCAN_B, 1024>>>(E);
    k_fill      <<<(E / 2 + 255) / 256, 256>>>(ei, E);
    k_gemm_mma  <<<NT2, 256>>>(x, b1, b2, out, 0);   // -> g_h (device-side)
    k_aggregate <<<(N_NODES + 7) / 8, 256>>>();
    k_gemm_mma  <<<NT2, 256>>>(x, b1, b2, out, 1);   // g_agg -> out
}